// round 14
// baseline (speedup 1.0000x reference)
#include <cuda_runtime.h>
#include <cuda_fp16.h>
#include <math.h>
#include <stdint.h>

#define NG 978
#define HD 300
#define NB 128
#define H2 512

// ---------------- scratch (no allocs allowed) ----------------
__device__ float d_deg[NG];
__device__ float d_bufA[NG * HD];
__device__ float d_bufB[NG * HD];
__device__ float d_bufC[NG * HD];
__device__ float d_hg[NG * H2];
__device__ float d_hm[NB * H2];
__device__ float d_pool[NB * H2];
__device__ __half d_w2h[H2 * H2];  // fp16 W2, chunk-blocked [k/32][n][32]
__device__ __half d_w3h[H2 * H2];  // fp16 W3, chunk-blocked [k/32][n][32]

// ---------------- helpers ----------------
__device__ __forceinline__ uint32_t smem_u32(const void* p) {
    uint32_t a;
    asm("{ .reg .u64 t; cvta.to.shared.u64 t, %1; cvt.u32.u64 %0, t; }" : "=r"(a) : "l"(p));
    return a;
}
__device__ __forceinline__ void cp_async16(uint32_t saddr, const void* gptr) {
    asm volatile("cp.async.cg.shared.global [%0], [%1], 16;" :: "r"(saddr), "l"(gptr));
}
__device__ __forceinline__ void cp_commit() {
    asm volatile("cp.async.commit_group;");
}
template <int N>
__device__ __forceinline__ void cp_wait() {
    asm volatile("cp.async.wait_group %0;" :: "n"(N));
}
__device__ __forceinline__ void mma_f16(float* c, const uint32_t* a, uint32_t b0, uint32_t b1) {
    asm volatile(
        "mma.sync.aligned.m16n8k16.row.col.f32.f16.f16.f32 "
        "{%0,%1,%2,%3}, {%4,%5,%6,%7}, {%8,%9}, {%0,%1,%2,%3};"
        : "+f"(c[0]), "+f"(c[1]), "+f"(c[2]), "+f"(c[3])
        : "r"(a[0]), "r"(a[1]), "r"(a[2]), "r"(a[3]), "r"(b0), "r"(b1));
}
__device__ __forceinline__ void ldsm_x4(uint32_t* r, uint32_t addr) {
    asm volatile("ldmatrix.sync.aligned.m8n8.x4.shared.b16 {%0,%1,%2,%3}, [%4];"
                 : "=r"(r[0]), "=r"(r[1]), "=r"(r[2]), "=r"(r[3]) : "r"(addr));
}
__device__ __forceinline__ void red_add_v4(float* gptr, float a, float b, float c, float d) {
    asm volatile("red.global.add.v4.f32 [%0], {%1, %2, %3, %4};"
                 :: "l"(gptr), "f"(a), "f"(b), "f"(c), "f"(d) : "memory");
}

// ---------------- fused prep: deg_init + fp16 weight conversion + pool zero ----
__global__ void k_prep(const float* __restrict__ f2w, const float* __restrict__ f3w,
                       __half* __restrict__ w2h, __half* __restrict__ w3h,
                       float* __restrict__ pool) {
    int i = blockIdx.x * blockDim.x + threadIdx.x;
    if (i < H2 * H2) {
        int k = i >> 9, n = i & 511;
        int o = ((k >> 5) << 14) + (n << 5) + (k & 31);
        w2h[o] = __float2half_rn(f2w[i]);
        w3h[o] = __float2half_rn(f3w[i]);
    }
    if (i < NG) d_deg[i] = 1.0f;
    if (i < NB * H2) pool[i] = 0.0f;
}
__global__ void k_deg_count(const int* __restrict__ dst, int E) {
    int i = blockIdx.x * blockDim.x + threadIdx.x;
    if (i < E) atomicAdd(&d_deg[dst[i]], 1.0f);
}
// out[dst] += in[src]*dinv[src]*dinv[dst], one red.v4 per (edge, float4)
__global__ void k_scatter_edges4(const float* __restrict__ in, float* __restrict__ outp,
                                 const int* __restrict__ src, const int* __restrict__ dst,
                                 int E) {
    int idx = blockIdx.x * blockDim.x + threadIdx.x;
    if (idx >= E * 75) return;
    int e = idx / 75;
    int f4 = idx - e * 75;
    int s = src[e], d = dst[e];
    float w = rsqrtf(d_deg[s]) * rsqrtf(d_deg[d]);
    float4 v = *(const float4*)(in + (size_t)s * HD + f4 * 4);
    red_add_v4(outp + (size_t)d * HD + f4 * 4, v.x * w, v.y * w, v.z * w, v.w * w);
}

// ---------------- 32x32-tile SGEMM, 256 threads, register double-buffer ------
// C = alpha*A@B (+bias if C2==null). If C2 != null (GCN fusion):
//   C  = A@B ; C2 = bias + (A@B)*dinv[m]^2   (dinv = rsqrtf(deg))
__global__ void __launch_bounds__(256) sgemm_t(
    const float* __restrict__ A, int lda,
    const float* __restrict__ B, int ldb,
    float* __restrict__ C, int ldc,
    int M, int N, int K,
    const float* __restrict__ bias, float alpha,
    float* __restrict__ C2) {
    __shared__ float As[16][33];
    __shared__ float Bs[16][32];
    const int tid = threadIdx.x;
    const int n0 = blockIdx.x * 32;
    const int m0 = blockIdx.y * 32;
    const int row = tid >> 3;          // 0..31
    const int col4 = (tid & 7) << 2;   // 0..28
    float acc[4] = {0.f, 0.f, 0.f, 0.f};

    int akk[2], ar[2], bc[2], bkk[2];
#pragma unroll
    for (int i = 0; i < 2; i++) {
        int e = tid + i * 256;
        akk[i] = e & 15; ar[i] = e >> 4;
        bc[i] = e & 31;  bkk[i] = e >> 5;
    }

    float ra[2], rb[2];
#pragma unroll
    for (int i = 0; i < 2; i++) {
        int gm = m0 + ar[i], gk = akk[i];
        ra[i] = (gm < M && gk < K) ? A[(size_t)gm * lda + gk] : 0.0f;
        int gn = n0 + bc[i], gk2 = bkk[i];
        rb[i] = (gn < N && gk2 < K) ? B[(size_t)gk2 * ldb + gn] : 0.0f;
    }

    for (int k0 = 0; k0 < K; k0 += 16) {
#pragma unroll
        for (int i = 0; i < 2; i++) {
            As[akk[i]][ar[i]] = ra[i];
            Bs[bkk[i]][bc[i]] = rb[i];
        }
        __syncthreads();
        int kn = k0 + 16;
        if (kn < K) {
#pragma unroll
            for (int i = 0; i < 2; i++) {
                int gm = m0 + ar[i], gk = kn + akk[i];
                ra[i] = (gm < M && gk < K) ? A[(size_t)gm * lda + gk] : 0.0f;
                int gn = n0 + bc[i], gk2 = kn + bkk[i];
                rb[i] = (gn < N && gk2 < K) ? B[(size_t)gk2 * ldb + gn] : 0.0f;
            }
        }
#pragma unroll
        for (int k = 0; k < 16; k++) {
            float a = As[k][row];
            float4 bv = *(const float4*)&Bs[k][col4];
            acc[0] = fmaf(a, bv.x, acc[0]);
            acc[1] = fmaf(a, bv.y, acc[1]);
            acc[2] = fmaf(a, bv.z, acc[2]);
            acc[3] = fmaf(a, bv.w, acc[3]);
        }
        __syncthreads();
    }
    int gm = m0 + row;
    if (gm < M) {
        float di2 = 0.0f;
        if (C2) { float di = rsqrtf(d_deg[gm]); di2 = di * di; }
#pragma unroll
        for (int c = 0; c < 4; c++) {
            int gn = n0 + col4 + c;
            if (gn >= N) continue;
            float v = alpha * acc[c];
            if (C2) {
                C[(size_t)gm * ldc + gn] = v;
                C2[(size_t)gm * ldc + gn] = bias[gn] + v * di2;
            } else {
                if (bias) v += bias[gn];
                C[(size_t)gm * ldc + gn] = v;
            }
        }
    }
}

// ---------------- fused FFN via mma.sync fp16 + ldmatrix ----------------
// Block = (32 genes, 1 batch), 256 threads / 8 warps, warp tile 32x64,
// 2 BLOCKS RESIDENT PER SM (115200 B <= half-SM SMEM). When one block sits
// in cp_wait/__syncthreads, the co-resident block's warps keep the SMSPs
// fed -> hides the per-chunk sync overhead a single 230KB block exposed.
// W double-buffered, distance-1 pipeline.
#define LDXH 520
#define WROWH 40                              // padded halves per n-row (80B)
#define X_BYTES (32 * LDXH * 2)               // 33280
#define WC_BYTES (512 * WROWH * 2)            // 40960
#define SMEM_FFN (X_BYTES + 2 * WC_BYTES)     // 115200 (<= 116224 half-SM)
#define NTILE_FFN 31                          // ceil(978/32)

__global__ void __launch_bounds__(256, 2) k_ffn_tc(
    const float* __restrict__ hg, const float* __restrict__ hm,
    const float* __restrict__ b1,
    const __half* __restrict__ W2h, const float* __restrict__ b2,
    const __half* __restrict__ W3h, const float* __restrict__ b3,
    float* __restrict__ pool)
{
    extern __shared__ unsigned char smem[];
    __half* Xs = (__half*)smem;
    const uint32_t sb = smem_u32(smem);
    const uint32_t wc_base = sb + X_BYTES;

    const int tid = threadIdx.x;
    const int lane = tid & 31;
    const int wid = tid >> 5;          // 0..7
    const int g = lane >> 2;
    const int t = lane & 3;
    const int colbase = wid * 64;      // 0..448
    const int b = blockIdx.y;
    const int g0 = blockIdx.x * 32;
    const int valid = min(32, NG - g0);

    // ldmatrix lane-address bases (m8n8.x4 lane->matrix mapping)
    const uint32_t a_base = sb +
        (uint32_t)((((lane & 7) + ((lane >> 3) & 1) * 8) * LDXH
                    + ((lane >> 4) & 1) * 8) * 2);
    const uint32_t b_lane_off =
        (uint32_t)((((colbase + (lane & 7) + ((lane >> 4) & 1) * 8) * WROWH)
                    + ((lane >> 3) & 1) * 8) * 2);

    // ---- fill X = half(relu(hg + hm + b1))  (32 rows x 128 float4) ----
    for (int i = tid; i < 32 * 128; i += 256) {
        int r = i >> 7, q = (i & 127) * 4;
        __half2 h01 = __floats2half2_rn(0.f, 0.f), h23 = h01;
        if (r < valid) {
            float4 a = *(const float4*)(hg + (size_t)(g0 + r) * H2 + q);
            float4 m = *(const float4*)(hm + (size_t)b * H2 + q);
            float4 c = *(const float4*)(b1 + q);
            h01 = __floats2half2_rn(fmaxf(a.x + m.x + c.x, 0.f), fmaxf(a.y + m.y + c.y, 0.f));
            h23 = __floats2half2_rn(fmaxf(a.z + m.z + c.z, 0.f), fmaxf(a.w + m.w + c.w, 0.f));
        }
        __half2* xp = (__half2*)(Xs + r * LDXH + q);
        xp[0] = h01;
        xp[1] = h23;
    }
    __syncthreads();

    float acc[2][8][4];

    // prologue: W2 chunk 0 -> buffer 0 (2048 x 16B segs, 8 per thread)
    for (int e = tid; e < 2048; e += 256) {
        int n = e >> 2, seg = e & 3;
        cp_async16(wc_base + (uint32_t)(n * 80 + seg * 16),
                   (const char*)W2h + n * 64 + seg * 16);
    }
    cp_commit();

    for (int layer = 0; layer < 2; ++layer) {
        const __half* W = layer ? W3h : W2h;
        const float* bias = layer ? b3 : b2;
#pragma unroll
        for (int rt = 0; rt < 2; ++rt)
#pragma unroll
            for (int ct = 0; ct < 8; ++ct)
#pragma unroll
                for (int j = 0; j < 4; ++j) acc[rt][ct][j] = 0.f;

        for (int kb = 0; kb < 16; ++kb) {
            cp_wait<0>();          // chunk kb resident
            __syncthreads();       // all warps done with buffer (kb+1)&1 (chunk kb-1)
            if (kb + 1 < 16) {     // issue chunk kb+1 into the other buffer
                const char* src = (const char*)(W + (kb + 1) * 16384);
                uint32_t dstb = wc_base + ((kb + 1) & 1) * WC_BYTES;
                for (int e = tid; e < 2048; e += 256) {
                    int n = e >> 2, seg = e & 3;
                    cp_async16(dstb + (uint32_t)(n * 80 + seg * 16), src + n * 64 + seg * 16);
                }
                cp_commit();
            }

            const uint32_t wchunk = wc_base + (kb & 1) * WC_BYTES + b_lane_off;
#pragma unroll
            for (int ks = 0; ks < 2; ++ks) {
                const uint32_t kbyte = (uint32_t)((kb * 32 + ks * 16) * 2);
                uint32_t a[2][4];
                ldsm_x4(a[0], a_base + kbyte);
                ldsm_x4(a[1], a_base + (uint32_t)(16 * LDXH * 2) + kbyte);
#pragma unroll
                for (int ctp = 0; ctp < 4; ++ctp) {
                    uint32_t bf[4];
                    ldsm_x4(bf, wchunk + (uint32_t)(ctp * 16 * WROWH * 2 + ks * 32));
                    mma_f16(acc[0][2 * ctp], a[0], bf[0], bf[1]);
                    mma_f16(acc[1][2 * ctp], a[1], bf[0], bf[1]);
                    mma_f16(acc[0][2 * ctp + 1], a[0], bf[2], bf[3]);
                    mma_f16(acc[1][2 * ctp + 1], a[1], bf[2], bf[3]);
                }
            }
        }
        __syncthreads();           // all warps finished all MMAs of this layer

        if (layer == 0) {
            // issue W3 chunk 0 NOW (both buffers consumed) -> overlaps epilogue
            for (int e = tid; e < 2048; e += 256) {
                int n = e >> 2, seg = e & 3;
                cp_async16(wc_base + (uint32_t)(n * 80 + seg * 16),
                           (const char*)W3h + n * 64 + seg * 16);
            }
            cp_commit();
            // X <- half(relu(acc + b2))
#pragma unroll
            for (int rt = 0; rt < 2; ++rt) {
                int r0 = rt * 16 + g;
#pragma unroll
                for (int ct = 0; ct < 8; ++ct) {
                    int col = colbase + ct * 8 + t * 2;
                    float ba = bias[col], bb = bias[col + 1];
                    *(__half2*)(Xs + (size_t)r0 * LDXH + col) =
                        __floats2half2_rn(fmaxf(acc[rt][ct][0] + ba, 0.f),
                                          fmaxf(acc[rt][ct][1] + bb, 0.f));
                    *(__half2*)(Xs + (size_t)(r0 + 8) * LDXH + col) =
                        __floats2half2_rn(fmaxf(acc[rt][ct][2] + ba, 0.f),
                                          fmaxf(acc[rt][ct][3] + bb, 0.f));
                }
            }
            __syncthreads();
        } else {
            // gene-sum of relu(acc + b3) over valid rows -> pool[b]
            float* red = (float*)(smem + X_BYTES);  // buffer 0, drained
            for (int i = tid; i < 512; i += 256) red[i] = 0.f;
            __syncthreads();
#pragma unroll
            for (int ct = 0; ct < 8; ++ct) {
                int col = colbase + ct * 8 + t * 2;
#pragma unroll
                for (int j = 0; j < 2; ++j) {
                    float bv = bias[col + j];
                    float s = 0.f;
#pragma unroll
                    for (int rt = 0; rt < 2; ++rt) {
                        int r0 = rt * 16 + g;
                        if (r0 < valid)     s += fmaxf(acc[rt][ct][j] + bv, 0.f);
                        if (r0 + 8 < valid) s += fmaxf(acc[rt][ct][2 + j] + bv, 0.f);
                    }
                    s += __shfl_xor_sync(0xFFFFFFFFu, s, 4);
                    s += __shfl_xor_sync(0xFFFFFFFFu, s, 8);
                    s += __shfl_xor_sync(0xFFFFFFFFu, s, 16);
                    if (g == 0) atomicAdd(&red[col + j], s);
                }
            }
            __syncthreads();
            for (int i = tid; i < 512; i += 256)
                atomicAdd(&pool[(size_t)b * H2 + i], red[i]);
        }
    }
}

// ---------------- launch ----------------
extern "C" void kernel_launch(void* const* d_in, const int* in_sizes, int n_in,
                              void* d_out, int out_size) {
    const float* mol  = (const float*)d_in[0];
    const float* gene = (const float*)d_in[1];
    const int*   ei   = (const int*)d_in[2];
    const float* g1w  = (const float*)d_in[3];
    const float* g1b  = (const float*)d_in[4];
    const float* g2w  = (const float*)d_in[5];
    const float* g2b  = (const float*)d_in[6];
    const float* f1w  = (const float*)d_in[7];
    const float* f1b  = (const float*)d_in[8];
    const float* f2w  = (const float*)d_in[9];
    const float* f2b  = (const float*)d_in[10];
    const float* f3w  = (const float*)d_in[11];
    const float* f3b  = (const float*)d_in[12];
    const float* f4w  = (const float*)d_in[13];
    const float* f4b  = (const float*)d_in[14];
    float* out = (float*)d_out;

    int E = in_sizes[2] / 2;
    const int* src = ei;
    const int* dst = ei + E;

    float *bufA, *bufB, *bufC, *hg, *hm, *pool;
    __half *w2h, *w3h;
    cudaGetSymbolAddress((void**)&bufA, d_bufA);
    cudaGetSymbolAddress((void**)&bufB, d_bufB);
    cudaGetSymbolAddress((void**)&bufC, d_bufC);
    cudaGetSymbolAddress((void**)&hg, d_hg);
    cudaGetSymbolAddress((void**)&hm, d_hm);
    cudaGetSymbolAddress((void**)&pool, d_pool);
    cudaGetSymbolAddress((void**)&w2h, d_w2h);
    cudaGetSymbolAddress((void**)&w3h, d_w3h);

    // prep (deg_init + fp16 weights + pool zero), then degree count
    k_prep<<<1024, 256>>>(f2w, f3w, w2h, w3h, pool);
    k_deg_count<<<(E + 255) / 256, 256>>>(dst, E);

    // GCN layer 1: bufA = gene@g1w (raw), bufB = g1b + bufA*dinv^2, then edges
    sgemm_t<<<dim3(10, 31), 256>>>(gene, HD, g1w, HD, bufA, HD, NG, HD, HD, g1b, 1.0f, bufB);
    k_scatter_edges4<<<(E * 75 + 255) / 256, 256>>>(bufA, bufB, src, dst, E);

    // GCN layer 2: bufA = bufB@g2w (raw), bufC = g2b + bufA*dinv^2, then edges
    sgemm_t<<<dim3(10, 31), 256>>>(bufB, HD, g2w, HD, bufA, HD, NG, HD, HD, g2b, 1.0f, bufC);
    k_scatter_edges4<<<(E * 75 + 255) / 256, 256>>>(bufA, bufC, src, dst, E);

    // ffn1 split: hg = g2 @ W1[:300], hm = mol @ W1[300:]
    sgemm_t<<<dim3(16, 31), 256>>>(bufC, HD, f1w, H2, hg, H2, NG, H2, HD, nullptr, 1.0f, nullptr);
    sgemm_t<<<dim3(16, 4), 256>>>(mol, HD, f1w + HD * H2, H2, hm, H2, NB, H2, HD, nullptr, 1.0f, nullptr);

    // fused ffn2+ffn3+mean-partial on fp16 tensor cores (2 blocks/SM)
    cudaFuncSetAttribute(k_ffn_tc, cudaFuncAttributeMaxDynamicSharedMemorySize, SMEM_FFN);
    k_ffn_tc<<<dim3(NTILE_FFN, NB), 256, SMEM_FFN>>>(hg, hm, f1b, w2h, f2b, w3h, f3b, pool);

    // out = (pool/978) @ ffn4_w + ffn4_b
    sgemm_t<<<dim3(31, 4), 256>>>(pool, H2, f4w, NG, out, NG, NB, NG, H2, f4b, 1.0f / 978.0f, nullptr);
}

// round 16
// speedup vs baseline: 1.0388x; 1.0388x over previous
#include <cuda_runtime.h>
#include <cuda_fp16.h>
#include <math.h>
#include <stdint.h>

#define NG 978
#define HD 300
#define NB 128
#define H2 512

// ---------------- scratch (no allocs allowed) ----------------
__device__ float d_deg[NG];
__device__ float d_bufA[NG * HD];
__device__ float d_bufB[NG * HD];
__device__ float d_bufC[NG * HD];
__device__ float d_hg[NG * H2];
__device__ float d_hm[NB * H2];
__device__ float d_pool[NB * H2];
__device__ __half d_w2h[H2 * H2];  // fp16 W2, chunk-blocked [k/32][n][32]
__device__ __half d_w3h[H2 * H2];  // fp16 W3, chunk-blocked [k/32][n][32]

// ---------------- helpers ----------------
__device__ __forceinline__ uint32_t smem_u32(const void* p) {
    uint32_t a;
    asm("{ .reg .u64 t; cvta.to.shared.u64 t, %1; cvt.u32.u64 %0, t; }" : "=r"(a) : "l"(p));
    return a;
}
__device__ __forceinline__ void cp_async16(uint32_t saddr, const void* gptr) {
    asm volatile("cp.async.cg.shared.global [%0], [%1], 16;" :: "r"(saddr), "l"(gptr));
}
__device__ __forceinline__ void cp_commit() {
    asm volatile("cp.async.commit_group;");
}
template <int N>
__device__ __forceinline__ void cp_wait() {
    asm volatile("cp.async.wait_group %0;" :: "n"(N));
}
__device__ __forceinline__ void mma_f16(float* c, const uint32_t* a, uint32_t b0, uint32_t b1) {
    asm volatile(
        "mma.sync.aligned.m16n8k16.row.col.f32.f16.f16.f32 "
        "{%0,%1,%2,%3}, {%4,%5,%6,%7}, {%8,%9}, {%0,%1,%2,%3};"
        : "+f"(c[0]), "+f"(c[1]), "+f"(c[2]), "+f"(c[3])
        : "r"(a[0]), "r"(a[1]), "r"(a[2]), "r"(a[3]), "r"(b0), "r"(b1));
}
__device__ __forceinline__ void ldsm_x4(uint32_t* r, uint32_t addr) {
    asm volatile("ldmatrix.sync.aligned.m8n8.x4.shared.b16 {%0,%1,%2,%3}, [%4];"
                 : "=r"(r[0]), "=r"(r[1]), "=r"(r[2]), "=r"(r[3]) : "r"(addr));
}
__device__ __forceinline__ void red_add_v4(float* gptr, float a, float b, float c, float d) {
    asm volatile("red.global.add.v4.f32 [%0], {%1, %2, %3, %4};"
                 :: "l"(gptr), "f"(a), "f"(b), "f"(c), "f"(d) : "memory");
}

// ---------------- fused prep: deg_init + fp16 weight conversion + pool zero ----
__global__ void k_prep(const float* __restrict__ f2w, const float* __restrict__ f3w,
                       __half* __restrict__ w2h, __half* __restrict__ w3h,
                       float* __restrict__ pool) {
    int i = blockIdx.x * blockDim.x + threadIdx.x;
    if (i < H2 * H2) {
        int k = i >> 9, n = i & 511;
        int o = ((k >> 5) << 14) + (n << 5) + (k & 31);
        w2h[o] = __float2half_rn(f2w[i]);
        w3h[o] = __float2half_rn(f3w[i]);
    }
    if (i < NG) d_deg[i] = 1.0f;
    if (i < NB * H2) pool[i] = 0.0f;
}
__global__ void k_deg_count(const int* __restrict__ dst, int E) {
    int i = blockIdx.x * blockDim.x + threadIdx.x;
    if (i < E) atomicAdd(&d_deg[dst[i]], 1.0f);
}
// out[dst] += in[src]*dinv[src]*dinv[dst], one red.v4 per (edge, float4)
__global__ void k_scatter_edges4(const float* __restrict__ in, float* __restrict__ outp,
                                 const int* __restrict__ src, const int* __restrict__ dst,
                                 int E) {
    int idx = blockIdx.x * blockDim.x + threadIdx.x;
    if (idx >= E * 75) return;
    int e = idx / 75;
    int f4 = idx - e * 75;
    int s = src[e], d = dst[e];
    float w = rsqrtf(d_deg[s]) * rsqrtf(d_deg[d]);
    float4 v = *(const float4*)(in + (size_t)s * HD + f4 * 4);
    red_add_v4(outp + (size_t)d * HD + f4 * 4, v.x * w, v.y * w, v.z * w, v.w * w);
}

// ---------------- cp.async-pipelined 32x32 SGEMM (GCN / ffn1) ----------------
// SAME 32x32 tile & grid as the proven sgemm_t; only the load path changes
// (scalar LDG -> 16B cp.async, 3 buffers, prefetch distance 2, one commit
// group per iteration). fmaf order unchanged -> bit-identical results.
// Requires (lda*4)%16==0 && (ldb*4)%16==0 (true for HD=300, H2=512 strides).
// Out-of-range segments aren't issued; garbage SMEM only feeds k>=kmax
// (never read: peeled tail) or columns gn>=N (never written).
__global__ void __launch_bounds__(256) sgemm_c(
    const float* __restrict__ A, int lda,
    const float* __restrict__ B, int ldb,
    float* __restrict__ C, int ldc,
    int M, int N, int K,
    const float* __restrict__ bias, float alpha,
    float* __restrict__ C2) {
    __shared__ float As[3][32][20];   // [buf][row][k16 + pad4]
    __shared__ float Bs[3][16][32];   // [buf][k][n]
    const int tid = threadIdx.x;
    const int n0 = blockIdx.x * 32;
    const int m0 = blockIdx.y * 32;
    const int row = tid >> 3;          // 0..31
    const int col4 = (tid & 7) << 2;   // 0..28
    const uint32_t as_base = smem_u32(&As[0][0][0]);
    const uint32_t bs_base = smem_u32(&Bs[0][0][0]);
    const int nchunks = (K + 15) >> 4;
    float acc[4] = {0.f, 0.f, 0.f, 0.f};

    // one 16B segment per thread: tid<128 -> A (32 rows x 4 segs),
    // tid>=128 -> B (16 k-rows x 8 segs)
    const bool isA = tid < 128;
    const int ar = tid >> 2, aseg = tid & 3;
    const int agm = m0 + ar;
    const int u = tid & 127;
    const int bkk = u >> 3, bseg = u & 7;
    const int bgn = n0 + bseg * 4;

    // prologue: chunks 0,1 -> buffers 0,1 (one commit each)
#pragma unroll
    for (int pc = 0; pc < 2; ++pc) {
        if (pc < nchunks) {
            int k0 = pc * 16;
            if (isA) {
                if (agm < M && k0 + aseg * 4 + 4 <= K)
                    cp_async16(as_base + (uint32_t)(((pc * 32 + ar) * 20 + aseg * 4) * 4),
                               A + (size_t)agm * lda + k0 + aseg * 4);
            } else {
                if (k0 + bkk < K && bgn + 4 <= N)
                    cp_async16(bs_base + (uint32_t)(((pc * 16 + bkk) * 32 + bseg * 4) * 4),
                               B + (size_t)(k0 + bkk) * ldb + bgn);
            }
        }
        cp_commit();
    }

    for (int c = 0; c < nchunks; ++c) {
        cp_wait<1>();          // chunk c resident
        __syncthreads();       // compute on chunk c-1 done -> buffer (c+2)%3 free
        int cn = c + 2;
        if (cn < nchunks) {
            int k0 = cn * 16, buf2 = cn % 3;
            if (isA) {
                if (agm < M && k0 + aseg * 4 + 4 <= K)
                    cp_async16(as_base + (uint32_t)(((buf2 * 32 + ar) * 20 + aseg * 4) * 4),
                               A + (size_t)agm * lda + k0 + aseg * 4);
            } else {
                if (k0 + bkk < K && bgn + 4 <= N)
                    cp_async16(bs_base + (uint32_t)(((buf2 * 16 + bkk) * 32 + bseg * 4) * 4),
                               B + (size_t)(k0 + bkk) * ldb + bgn);
            }
        }
        cp_commit();           // unconditional: uniform group counting

        const int buf = c % 3;
        int kmax = K - c * 16;
        if (kmax >= 16) {
#pragma unroll
            for (int k = 0; k < 16; ++k) {
                float a = As[buf][row][k];
                float4 bv = *(const float4*)&Bs[buf][k][col4];
                acc[0] = fmaf(a, bv.x, acc[0]);
                acc[1] = fmaf(a, bv.y, acc[1]);
                acc[2] = fmaf(a, bv.z, acc[2]);
                acc[3] = fmaf(a, bv.w, acc[3]);
            }
        } else {
            for (int k = 0; k < kmax; ++k) {
                float a = As[buf][row][k];
                float4 bv = *(const float4*)&Bs[buf][k][col4];
                acc[0] = fmaf(a, bv.x, acc[0]);
                acc[1] = fmaf(a, bv.y, acc[1]);
                acc[2] = fmaf(a, bv.z, acc[2]);
                acc[3] = fmaf(a, bv.w, acc[3]);
            }
        }
    }
    cp_wait<0>();

    int gm = m0 + row;
    if (gm < M) {
        float di2 = 0.0f;
        if (C2) { float di = rsqrtf(d_deg[gm]); di2 = di * di; }
#pragma unroll
        for (int c = 0; c < 4; c++) {
            int gn = n0 + col4 + c;
            if (gn >= N) continue;
            float v = alpha * acc[c];
            if (C2) {
                C[(size_t)gm * ldc + gn] = v;
                C2[(size_t)gm * ldc + gn] = bias[gn] + v * di2;
            } else {
                if (bias) v += bias[gn];
                C[(size_t)gm * ldc + gn] = v;
            }
        }
    }
}

// ---------------- 32x32-tile SGEMM (ffn4 only: f4w rows not 16B-aligned) -----
__global__ void __launch_bounds__(256) sgemm_t(
    const float* __restrict__ A, int lda,
    const float* __restrict__ B, int ldb,
    float* __restrict__ C, int ldc,
    int M, int N, int K,
    const float* __restrict__ bias, float alpha) {
    __shared__ float As[16][33];
    __shared__ float Bs[16][32];
    const int tid = threadIdx.x;
    const int n0 = blockIdx.x * 32;
    const int m0 = blockIdx.y * 32;
    const int row = tid >> 3;
    const int col4 = (tid & 7) << 2;
    float acc[4] = {0.f, 0.f, 0.f, 0.f};

    int akk[2], ar[2], bc[2], bkk[2];
#pragma unroll
    for (int i = 0; i < 2; i++) {
        int e = tid + i * 256;
        akk[i] = e & 15; ar[i] = e >> 4;
        bc[i] = e & 31;  bkk[i] = e >> 5;
    }
    float ra[2], rb[2];
#pragma unroll
    for (int i = 0; i < 2; i++) {
        int gm = m0 + ar[i], gk = akk[i];
        ra[i] = (gm < M && gk < K) ? A[(size_t)gm * lda + gk] : 0.0f;
        int gn = n0 + bc[i], gk2 = bkk[i];
        rb[i] = (gn < N && gk2 < K) ? B[(size_t)gk2 * ldb + gn] : 0.0f;
    }
    for (int k0 = 0; k0 < K; k0 += 16) {
#pragma unroll
        for (int i = 0; i < 2; i++) {
            As[akk[i]][ar[i]] = ra[i];
            Bs[bkk[i]][bc[i]] = rb[i];
        }
        __syncthreads();
        int kn = k0 + 16;
        if (kn < K) {
#pragma unroll
            for (int i = 0; i < 2; i++) {
                int gm = m0 + ar[i], gk = kn + akk[i];
                ra[i] = (gm < M && gk < K) ? A[(size_t)gm * lda + gk] : 0.0f;
                int gn = n0 + bc[i], gk2 = kn + bkk[i];
                rb[i] = (gn < N && gk2 < K) ? B[(size_t)gk2 * ldb + gn] : 0.0f;
            }
        }
#pragma unroll
        for (int k = 0; k < 16; k++) {
            float a = As[k][row];
            float4 bv = *(const float4*)&Bs[k][col4];
            acc[0] = fmaf(a, bv.x, acc[0]);
            acc[1] = fmaf(a, bv.y, acc[1]);
            acc[2] = fmaf(a, bv.z, acc[2]);
            acc[3] = fmaf(a, bv.w, acc[3]);
        }
        __syncthreads();
    }
    int gm = m0 + row;
    if (gm < M) {
#pragma unroll
        for (int c = 0; c < 4; c++) {
            int gn = n0 + col4 + c;
            if (gn >= N) continue;
            float v = alpha * acc[c];
            if (bias) v += bias[gn];
            C[(size_t)gm * ldc + gn] = v;
        }
    }
}

// ---------------- fused FFN via mma.sync fp16 + ldmatrix (round-12 exact) ----
// Block = (64 genes, 1 batch), 512 threads / 16 warps, warp tile 32x64.
// X [64][520] half resident in SMEM across both 512x512 layers.
// W streamed in k=32 chunks (chunk-blocked global layout) via cp.async,
// quad-buffered; SMEM chunk layout [n][32] halves, 80B padded rows.
#define LDXH 520
#define WROWH 40                              // padded halves per n-row (80B)
#define X_BYTES (64 * LDXH * 2)               // 66560
#define WC_BYTES (512 * WROWH * 2)            // 40960
#define SMEM_FFN (X_BYTES + 4 * WC_BYTES)     // 230400 (<= 232448 max)

__global__ void __launch_bounds__(512, 1) k_ffn_tc(
    const float* __restrict__ hg, const float* __restrict__ hm,
    const float* __restrict__ b1,
    const __half* __restrict__ W2h, const float* __restrict__ b2,
    const __half* __restrict__ W3h, const float* __restrict__ b3,
    float* __restrict__ pool)
{
    extern __shared__ unsigned char smem[];
    __half* Xs = (__half*)smem;
    const uint32_t sb = smem_u32(smem);
    const uint32_t wc_base = sb + X_BYTES;

    const int tid = threadIdx.x;
    const int lane = tid & 31;
    const int wid = tid >> 5;
    const int g = lane >> 2;
    const int t = lane & 3;
    const int rowbase = (wid >> 3) * 32;   // 0 or 32
    const int colbase = (wid & 7) * 64;    // 0..448
    const int b = blockIdx.y;
    const int g0 = blockIdx.x * 64;
    const int valid = min(64, NG - g0);

    // ldmatrix lane-address bases (m8n8.x4 lane->matrix mapping)
    const uint32_t a_base = sb +
        (uint32_t)(((rowbase + (lane & 7) + ((lane >> 3) & 1) * 8) * LDXH
                    + ((lane >> 4) & 1) * 8) * 2);
    const uint32_t b_lane_off =
        (uint32_t)((((colbase + (lane & 7) + ((lane >> 4) & 1) * 8) * WROWH)
                    + ((lane >> 3) & 1) * 8) * 2);

    // ---- fill X = half(relu(hg + hm + b1)) ----
    for (int i = tid; i < 64 * 128; i += 512) {
        int r = i >> 7, q = (i & 127) * 4;
        __half2 h01 = __floats2half2_rn(0.f, 0.f), h23 = h01;
        if (r < valid) {
            float4 a = *(const float4*)(hg + (size_t)(g0 + r) * H2 + q);
            float4 m = *(const float4*)(hm + (size_t)b * H2 + q);
            float4 c = *(const float4*)(b1 + q);
            h01 = __floats2half2_rn(fmaxf(a.x + m.x + c.x, 0.f), fmaxf(a.y + m.y + c.y, 0.f));
            h23 = __floats2half2_rn(fmaxf(a.z + m.z + c.z, 0.f), fmaxf(a.w + m.w + c.w, 0.f));
        }
        __half2* xp = (__half2*)(Xs + r * LDXH + q);
        xp[0] = h01;
        xp[1] = h23;
    }
    __syncthreads();

    float acc[2][8][4];

    for (int layer = 0; layer < 2; ++layer) {
        const __half* W = layer ? W3h : W2h;
        const float* bias = layer ? b3 : b2;
#pragma unroll
        for (int rt = 0; rt < 2; ++rt)
#pragma unroll
            for (int ct = 0; ct < 8; ++ct)
#pragma unroll
                for (int j = 0; j < 4; ++j) acc[rt][ct][j] = 0.f;

        // prologue: chunks 0,1,2 -> buffers 0,1,2 (chunk = 512 n-rows x 64B)
#pragma unroll
        for (int pc = 0; pc < 3; ++pc) {
            const char* src = (const char*)(W + pc * 16384);
            uint32_t dstb = wc_base + pc * WC_BYTES;
            for (int e = tid; e < 2048; e += 512) {
                int n = e >> 2, seg = e & 3;
                cp_async16(dstb + (uint32_t)(n * 80 + seg * 16), src + n * 64 + seg * 16);
            }
            cp_commit();
        }

        for (int kb = 0; kb < 16; ++kb) {
            cp_wait<2>();          // chunk kb resident
            __syncthreads();       // all warps done reading buffer (kb+3)&3 (== kb-1)
            if (kb + 3 < 16) {
                const char* src = (const char*)(W + (kb + 3) * 16384);
                uint32_t dstb = wc_base + ((kb + 3) & 3) * WC_BYTES;
                for (int e = tid; e < 2048; e += 512) {
                    int n = e >> 2, seg = e & 3;
                    cp_async16(dstb + (uint32_t)(n * 80 + seg * 16), src + n * 64 + seg * 16);
                }
            }
            cp_commit();

            const uint32_t wchunk = wc_base + (kb & 3) * WC_BYTES + b_lane_off;
#pragma unroll
            for (int ks = 0; ks < 2; ++ks) {
                const uint32_t kbyte = (uint32_t)((kb * 32 + ks * 16) * 2);
                uint32_t a[2][4];
                ldsm_x4(a[0], a_base + kbyte);
                ldsm_x4(a[1], a_base + (uint32_t)(16 * LDXH * 2) + kbyte);
#pragma unroll
                for (int ctp = 0; ctp < 4; ++ctp) {
                    uint32_t bf[4];
                    ldsm_x4(bf, wchunk + (uint32_t)(ctp * 16 * WROWH * 2 + ks * 32));
                    mma_f16(acc[0][2 * ctp], a[0], bf[0], bf[1]);
                    mma_f16(acc[1][2 * ctp], a[1], bf[0], bf[1]);
                    mma_f16(acc[0][2 * ctp + 1], a[0], bf[2], bf[3]);
                    mma_f16(acc[1][2 * ctp + 1], a[1], bf[2], bf[3]);
                }
            }
        }
        cp_wait<0>();
        __syncthreads();

        if (layer == 0) {
            // X <- half(relu(acc + b2))
#pragma unroll
            for (int rt = 0; rt < 2; ++rt) {
                int r0 = rowbase + rt * 16 + g;
#pragma unroll
                for (int ct = 0; ct < 8; ++ct) {
                    int col = colbase + ct * 8 + t * 2;
                    float ba = bias[col], bb = bias[col + 1];
                    *(__half2*)(Xs + (size_t)r0 * LDXH + col) =
                        __floats2half2_rn(fmaxf(acc[rt][ct][0] + ba, 0.f),
                                          fmaxf(acc[rt][ct][1] + bb, 0.f));
                    *(__half2*)(Xs + (size_t)(r0 + 8) * LDXH + col) =
                        __floats2half2_rn(fmaxf(acc[rt][ct][2] + ba, 0.f),
                                          fmaxf(acc[rt][ct][3] + bb, 0.f));
                }
            }
            __syncthreads();
        } else {
            // gene-sum of relu(acc + b3) over valid rows -> pool[b]
            float* red = (float*)(smem + X_BYTES);  // reuse buffer 0 (drained)
            if (tid < 512) red[tid] = 0.f;
            __syncthreads();
#pragma unroll
            for (int ct = 0; ct < 8; ++ct) {
                int col = colbase + ct * 8 + t * 2;
#pragma unroll
                for (int j = 0; j < 2; ++j) {
                    float bv = bias[col + j];
                    float s = 0.f;
#pragma unroll
                    for (int rt = 0; rt < 2; ++rt) {
                        int r0 = rowbase + rt * 16 + g;
                        if (r0 < valid)     s += fmaxf(acc[rt][ct][j] + bv, 0.f);
                        if (r0 + 8 < valid) s += fmaxf(acc[rt][ct][2 + j] + bv, 0.f);
                    }
                    s += __shfl_xor_sync(0xFFFFFFFFu, s, 4);
                    s += __shfl_xor_sync(0xFFFFFFFFu, s, 8);
                    s += __shfl_xor_sync(0xFFFFFFFFu, s, 16);
                    if (g == 0) atomicAdd(&red[col + j], s);
                }
            }
            __syncthreads();
            if (tid < 512) atomicAdd(&pool[(size_t)b * H2 + tid], red[tid]);
        }
    }
}

// ---------------- launch ----------------
extern "C" void kernel_launch(void* const* d_in, const int* in_sizes, int n_in,
                              void* d_out, int out_size) {
    const float* mol  = (const float*)d_in[0];
    const float* gene = (const float*)d_in[1];
    const int*   ei   = (const int*)d_in[2];
    const float* g1w  = (const float*)d_in[3];
    const float* g1b  = (const float*)d_in[4];
    const float* g2w  = (const float*)d_in[5];
    const float* g2b  = (const float*)d_in[6];
    const float* f1w  = (const float*)d_in[7];
    const float* f1b  = (const float*)d_in[8];
    const float* f2w  = (const float*)d_in[9];
    const float* f2b  = (const float*)d_in[10];
    const float* f3w  = (const float*)d_in[11];
    const float* f3b  = (const float*)d_in[12];
    const float* f4w  = (const float*)d_in[13];
    const float* f4b  = (const float*)d_in[14];
    float* out = (float*)d_out;

    int E = in_sizes[2] / 2;
    const int* src = ei;
    const int* dst = ei + E;

    float *bufA, *bufB, *bufC, *hg, *hm, *pool;
    __half *w2h, *w3h;
    cudaGetSymbolAddress((void**)&bufA, d_bufA);
    cudaGetSymbolAddress((void**)&bufB, d_bufB);
    cudaGetSymbolAddress((void**)&bufC, d_bufC);
    cudaGetSymbolAddress((void**)&hg, d_hg);
    cudaGetSymbolAddress((void**)&hm, d_hm);
    cudaGetSymbolAddress((void**)&pool, d_pool);
    cudaGetSymbolAddress((void**)&w2h, d_w2h);
    cudaGetSymbolAddress((void**)&w3h, d_w3h);

    // prep (deg_init + fp16 weights + pool zero), then degree count
    k_prep<<<1024, 256>>>(f2w, f3w, w2h, w3h, pool);
    k_deg_count<<<(E + 255) / 256, 256>>>(dst, E);

    // GCN layer 1: bufA = gene@g1w (raw), bufB = g1b + bufA*dinv^2, then edges
    sgemm_c<<<dim3(10, 31), 256>>>(gene, HD, g1w, HD, bufA, HD, NG, HD, HD, g1b, 1.0f, bufB);
    k_scatter_edges4<<<(E * 75 + 255) / 256, 256>>>(bufA, bufB, src, dst, E);

    // GCN layer 2: bufA = bufB@g2w (raw), bufC = g2b + bufA*dinv^2, then edges
    sgemm_c<<<dim3(10, 31), 256>>>(bufB, HD, g2w, HD, bufA, HD, NG, HD, HD, g2b, 1.0f, bufC);
    k_scatter_edges4<<<(E * 75 + 255) / 256, 256>>>(bufA, bufC, src, dst, E);

    // ffn1 split: hg = g2 @ W1[:300], hm = mol @ W1[300:]
    sgemm_c<<<dim3(16, 31), 256>>>(bufC, HD, f1w, H2, hg, H2, NG, H2, HD, nullptr, 1.0f, nullptr);
    sgemm_c<<<dim3(16, 4), 256>>>(mol, HD, f1w + HD * H2, H2, hm, H2, NB, H2, HD, nullptr, 1.0f, nullptr);

    // fused ffn2+ffn3+mean-partial on fp16 tensor cores
    cudaFuncSetAttribute(k_ffn_tc, cudaFuncAttributeMaxDynamicSharedMemorySize, SMEM_FFN);
    k_ffn_tc<<<dim3(16, NB), 512, SMEM_FFN>>>(hg, hm, f1b, w2h, f2b, w3h, f3b, pool);

    // out = (pool/978) @ ffn4_w + ffn4_b  (f4w rows not 16B-aligned -> sgemm_t)
    sgemm_t<<<dim3(31, 4), 256>>>(pool, H2, f4w, NG, out, NG, NB, NG, H2, f4b, 1.0f / 978.0f);
}

// round 17
// speedup vs baseline: 1.0803x; 1.0400x over previous
#include <cuda_runtime.h>
#include <cuda_fp16.h>
#include <math.h>
#include <stdint.h>

#define NG 978
#define HD 300
#define NB 128
#define H2 512

// ---------------- scratch (no allocs allowed) ----------------
__device__ float d_deg[NG];
__device__ float d_bufA[NG * HD];
__device__ float d_bufB[NG * HD];
__device__ float d_bufC[NG * HD];
__device__ float d_hg[NG * H2];
__device__ float d_hm[NB * H2];
__device__ float d_pool[NB * H2];
__device__ float d_f4p[H2 * 980];  // zero-padded ffn4_w, 980-float rows (16B-aligned)
__device__ __half d_w2h[H2 * H2];  // fp16 W2, chunk-blocked [k/32][n][32]
__device__ __half d_w3h[H2 * H2];  // fp16 W3, chunk-blocked [k/32][n][32]

// ---------------- helpers ----------------
__device__ __forceinline__ uint32_t smem_u32(const void* p) {
    uint32_t a;
    asm("{ .reg .u64 t; cvta.to.shared.u64 t, %1; cvt.u32.u64 %0, t; }" : "=r"(a) : "l"(p));
    return a;
}
__device__ __forceinline__ void cp_async16(uint32_t saddr, const void* gptr) {
    asm volatile("cp.async.cg.shared.global [%0], [%1], 16;" :: "r"(saddr), "l"(gptr));
}
__device__ __forceinline__ void cp_commit() {
    asm volatile("cp.async.commit_group;");
}
template <int N>
__device__ __forceinline__ void cp_wait() {
    asm volatile("cp.async.wait_group %0;" :: "n"(N));
}
__device__ __forceinline__ void mma_f16(float* c, const uint32_t* a, uint32_t b0, uint32_t b1) {
    asm volatile(
        "mma.sync.aligned.m16n8k16.row.col.f32.f16.f16.f32 "
        "{%0,%1,%2,%3}, {%4,%5,%6,%7}, {%8,%9}, {%0,%1,%2,%3};"
        : "+f"(c[0]), "+f"(c[1]), "+f"(c[2]), "+f"(c[3])
        : "r"(a[0]), "r"(a[1]), "r"(a[2]), "r"(a[3]), "r"(b0), "r"(b1));
}
__device__ __forceinline__ void ldsm_x4(uint32_t* r, uint32_t addr) {
    asm volatile("ldmatrix.sync.aligned.m8n8.x4.shared.b16 {%0,%1,%2,%3}, [%4];"
                 : "=r"(r[0]), "=r"(r[1]), "=r"(r[2]), "=r"(r[3]) : "r"(addr));
}
__device__ __forceinline__ void red_add_v4(float* gptr, float a, float b, float c, float d) {
    asm volatile("red.global.add.v4.f32 [%0], {%1, %2, %3, %4};"
                 :: "l"(gptr), "f"(a), "f"(b), "f"(c), "f"(d) : "memory");
}

// ---------------- fused prep: deg_init + fp16 weights + pool zero + f4 pad ----
__global__ void k_prep(const float* __restrict__ f2w, const float* __restrict__ f3w,
                       const float* __restrict__ f4w,
                       __half* __restrict__ w2h, __half* __restrict__ w3h,
                       float* __restrict__ pool) {
    int i = blockIdx.x * blockDim.x + threadIdx.x;
    if (i < H2 * H2) {
        int k = i >> 9, n = i & 511;
        int o = ((k >> 5) << 14) + (n << 5) + (k & 31);
        w2h[o] = __float2half_rn(f2w[i]);
        w3h[o] = __float2half_rn(f3w[i]);
    }
    if (i < NG) d_deg[i] = 1.0f;
    if (i < NB * H2) pool[i] = 0.0f;
    // padded copy of f4w: [512][980], cols 978,979 zero
    for (int j = i; j < H2 * 980; j += 262144) {
        int k = j / 980, n = j - k * 980;
        d_f4p[j] = (n < NG) ? f4w[(size_t)k * NG + n] : 0.0f;
    }
}
__global__ void k_deg_count(const int* __restrict__ dst, int E) {
    int i = blockIdx.x * blockDim.x + threadIdx.x;
    if (i < E) atomicAdd(&d_deg[dst[i]], 1.0f);
}
// out[dst] += in[src]*dinv[src]*dinv[dst], one red.v4 per (edge, float4)
__global__ void k_scatter_edges4(const float* __restrict__ in, float* __restrict__ outp,
                                 const int* __restrict__ src, const int* __restrict__ dst,
                                 int E) {
    int idx = blockIdx.x * blockDim.x + threadIdx.x;
    if (idx >= E * 75) return;
    int e = idx / 75;
    int f4 = idx - e * 75;
    int s = src[e], d = dst[e];
    float w = rsqrtf(d_deg[s]) * rsqrtf(d_deg[d]);
    float4 v = *(const float4*)(in + (size_t)s * HD + f4 * 4);
    red_add_v4(outp + (size_t)d * HD + f4 * 4, v.x * w, v.y * w, v.z * w, v.w * w);
}

// ---------------- cp.async-pipelined 32x32 SGEMM (GCN / ffn1 / ffn4) ---------
// Requires (lda*4)%16==0 && (ldb*4)%16==0. Nw = write bound (<= N); padded
// N lets unaligned-width outputs (ffn4) use the aligned path.
__global__ void __launch_bounds__(256) sgemm_c(
    const float* __restrict__ A, int lda,
    const float* __restrict__ B, int ldb,
    float* __restrict__ C, int ldc,
    int M, int N, int K,
    const float* __restrict__ bias, float alpha,
    float* __restrict__ C2, int Nw) {
    __shared__ float As[3][32][20];   // [buf][row][k16 + pad4]
    __shared__ float Bs[3][16][32];   // [buf][k][n]
    const int tid = threadIdx.x;
    const int n0 = blockIdx.x * 32;
    const int m0 = blockIdx.y * 32;
    const int row = tid >> 3;          // 0..31
    const int col4 = (tid & 7) << 2;   // 0..28
    const uint32_t as_base = smem_u32(&As[0][0][0]);
    const uint32_t bs_base = smem_u32(&Bs[0][0][0]);
    const int nchunks = (K + 15) >> 4;
    float acc[4] = {0.f, 0.f, 0.f, 0.f};

    const bool isA = tid < 128;
    const int ar = tid >> 2, aseg = tid & 3;
    const int agm = m0 + ar;
    const int u = tid & 127;
    const int bkk = u >> 3, bseg = u & 7;
    const int bgn = n0 + bseg * 4;

    // prologue: chunks 0,1 -> buffers 0,1 (one commit each)
#pragma unroll
    for (int pc = 0; pc < 2; ++pc) {
        if (pc < nchunks) {
            int k0 = pc * 16;
            if (isA) {
                if (agm < M && k0 + aseg * 4 + 4 <= K)
                    cp_async16(as_base + (uint32_t)(((pc * 32 + ar) * 20 + aseg * 4) * 4),
                               A + (size_t)agm * lda + k0 + aseg * 4);
            } else {
                if (k0 + bkk < K && bgn + 4 <= N)
                    cp_async16(bs_base + (uint32_t)(((pc * 16 + bkk) * 32 + bseg * 4) * 4),
                               B + (size_t)(k0 + bkk) * ldb + bgn);
            }
        }
        cp_commit();
    }

    for (int c = 0; c < nchunks; ++c) {
        cp_wait<1>();
        __syncthreads();
        int cn = c + 2;
        if (cn < nchunks) {
            int k0 = cn * 16, buf2 = cn % 3;
            if (isA) {
                if (agm < M && k0 + aseg * 4 + 4 <= K)
                    cp_async16(as_base + (uint32_t)(((buf2 * 32 + ar) * 20 + aseg * 4) * 4),
                               A + (size_t)agm * lda + k0 + aseg * 4);
            } else {
                if (k0 + bkk < K && bgn + 4 <= N)
                    cp_async16(bs_base + (uint32_t)(((buf2 * 16 + bkk) * 32 + bseg * 4) * 4),
                               B + (size_t)(k0 + bkk) * ldb + bgn);
            }
        }
        cp_commit();

        const int buf = c % 3;
        int kmax = K - c * 16;
        if (kmax >= 16) {
#pragma unroll
            for (int k = 0; k < 16; ++k) {
                float a = As[buf][row][k];
                float4 bv = *(const float4*)&Bs[buf][k][col4];
                acc[0] = fmaf(a, bv.x, acc[0]);
                acc[1] = fmaf(a, bv.y, acc[1]);
                acc[2] = fmaf(a, bv.z, acc[2]);
                acc[3] = fmaf(a, bv.w, acc[3]);
            }
        } else {
            for (int k = 0; k < kmax; ++k) {
                float a = As[buf][row][k];
                float4 bv = *(const float4*)&Bs[buf][k][col4];
                acc[0] = fmaf(a, bv.x, acc[0]);
                acc[1] = fmaf(a, bv.y, acc[1]);
                acc[2] = fmaf(a, bv.z, acc[2]);
                acc[3] = fmaf(a, bv.w, acc[3]);
            }
        }
    }
    cp_wait<0>();

    int gm = m0 + row;
    if (gm < M) {
        float di2 = 0.0f;
        if (C2) { float di = rsqrtf(d_deg[gm]); di2 = di * di; }
#pragma unroll
        for (int c = 0; c < 4; c++) {
            int gn = n0 + col4 + c;
            if (gn >= Nw) continue;
            float v = alpha * acc[c];
            if (C2) {
                C[(size_t)gm * ldc + gn] = v;
                C2[(size_t)gm * ldc + gn] = bias[gn] + v * di2;
            } else {
                if (bias) v += bias[gn];
                C[(size_t)gm * ldc + gn] = v;
            }
        }
    }
}

// ---------------- fused FFN via mma.sync fp16 + ldmatrix ----------------
// Round-12 geometry (512 threads, 16 warps, warp tile 32x64, 4x40KB slots);
// CHANGE: chunks consumed in PAIRS (one commit group = 2 subchunks = 64 k),
// one wait + one __syncthreads per pair -> 8 sync points/layer instead of 16.
// MMA order unchanged -> bit-identical numerics. W traffic unchanged.
#define LDXH 520
#define WROWH 40                              // padded halves per n-row (80B)
#define X_BYTES (64 * LDXH * 2)               // 66560
#define WC_BYTES (512 * WROWH * 2)            // 40960
#define SMEM_FFN (X_BYTES + 4 * WC_BYTES)     // 230400 (<= 232448 max)

__global__ void __launch_bounds__(512, 1) k_ffn_tc(
    const float* __restrict__ hg, const float* __restrict__ hm,
    const float* __restrict__ b1,
    const __half* __restrict__ W2h, const float* __restrict__ b2,
    const __half* __restrict__ W3h, const float* __restrict__ b3,
    float* __restrict__ pool)
{
    extern __shared__ unsigned char smem[];
    __half* Xs = (__half*)smem;
    const uint32_t sb = smem_u32(smem);
    const uint32_t wc_base = sb + X_BYTES;

    const int tid = threadIdx.x;
    const int lane = tid & 31;
    const int wid = tid >> 5;
    const int g = lane >> 2;
    const int t = lane & 3;
    const int rowbase = (wid >> 3) * 32;   // 0 or 32
    const int colbase = (wid & 7) * 64;    // 0..448
    const int b = blockIdx.y;
    const int g0 = blockIdx.x * 64;
    const int valid = min(64, NG - g0);

    // ldmatrix lane-address bases (m8n8.x4 lane->matrix mapping)
    const uint32_t a_base = sb +
        (uint32_t)(((rowbase + (lane & 7) + ((lane >> 3) & 1) * 8) * LDXH
                    + ((lane >> 4) & 1) * 8) * 2);
    const uint32_t b_lane_off =
        (uint32_t)((((colbase + (lane & 7) + ((lane >> 4) & 1) * 8) * WROWH)
                    + ((lane >> 3) & 1) * 8) * 2);

    // ---- fill X = half(relu(hg + hm + b1)) ----
    for (int i = tid; i < 64 * 128; i += 512) {
        int r = i >> 7, q = (i & 127) * 4;
        __half2 h01 = __floats2half2_rn(0.f, 0.f), h23 = h01;
        if (r < valid) {
            float4 a = *(const float4*)(hg + (size_t)(g0 + r) * H2 + q);
            float4 m = *(const float4*)(hm + (size_t)b * H2 + q);
            float4 c = *(const float4*)(b1 + q);
            h01 = __floats2half2_rn(fmaxf(a.x + m.x + c.x, 0.f), fmaxf(a.y + m.y + c.y, 0.f));
            h23 = __floats2half2_rn(fmaxf(a.z + m.z + c.z, 0.f), fmaxf(a.w + m.w + c.w, 0.f));
        }
        __half2* xp = (__half2*)(Xs + r * LDXH + q);
        xp[0] = h01;
        xp[1] = h23;
    }
    __syncthreads();

    float acc[2][8][4];

    for (int layer = 0; layer < 2; ++layer) {
        const __half* W = layer ? W3h : W2h;
        const float* bias = layer ? b3 : b2;
#pragma unroll
        for (int rt = 0; rt < 2; ++rt)
#pragma unroll
            for (int ct = 0; ct < 8; ++ct)
#pragma unroll
                for (int j = 0; j < 4; ++j) acc[rt][ct][j] = 0.f;

        // prologue: subchunks 0,1 (pair 0) -> slots 0,1, ONE commit group
        for (int sc = 0; sc < 2; ++sc) {
            const char* src = (const char*)(W + sc * 16384);
            uint32_t dstb = wc_base + sc * WC_BYTES;
            for (int e = tid; e < 2048; e += 512) {
                int n = e >> 2, seg = e & 3;
                cp_async16(dstb + (uint32_t)(n * 80 + seg * 16), src + n * 64 + seg * 16);
            }
        }
        cp_commit();

        for (int kb2 = 0; kb2 < 8; ++kb2) {
            cp_wait<0>();          // pair kb2 resident (only pending group)
            __syncthreads();       // pair kb2-1's slots fully consumed
            if (kb2 + 1 < 8) {     // issue pair kb2+1 into the other slot pair
#pragma unroll
                for (int s2 = 0; s2 < 2; ++s2) {
                    int sc = (kb2 + 1) * 2 + s2;
                    const char* src = (const char*)(W + sc * 16384);
                    uint32_t dstb = wc_base + (sc & 3) * WC_BYTES;
                    for (int e = tid; e < 2048; e += 512) {
                        int n = e >> 2, seg = e & 3;
                        cp_async16(dstb + (uint32_t)(n * 80 + seg * 16), src + n * 64 + seg * 16);
                    }
                }
                cp_commit();
            }
#pragma unroll
            for (int s2 = 0; s2 < 2; ++s2) {
                const int kb = kb2 * 2 + s2;
                const uint32_t wchunk = wc_base + (kb & 3) * WC_BYTES + b_lane_off;
#pragma unroll
                for (int ks = 0; ks < 2; ++ks) {
                    const uint32_t kbyte = (uint32_t)((kb * 32 + ks * 16) * 2);
                    uint32_t a[2][4];
                    ldsm_x4(a[0], a_base + kbyte);
                    ldsm_x4(a[1], a_base + (uint32_t)(16 * LDXH * 2) + kbyte);
#pragma unroll
                    for (int ctp = 0; ctp < 4; ++ctp) {
                        uint32_t bf[4];
                        ldsm_x4(bf, wchunk + (uint32_t)(ctp * 16 * WROWH * 2 + ks * 32));
                        mma_f16(acc[0][2 * ctp], a[0], bf[0], bf[1]);
                        mma_f16(acc[1][2 * ctp], a[1], bf[0], bf[1]);
                        mma_f16(acc[0][2 * ctp + 1], a[0], bf[2], bf[3]);
                        mma_f16(acc[1][2 * ctp + 1], a[1], bf[2], bf[3]);
                    }
                }
            }
        }
        cp_wait<0>();
        __syncthreads();

        if (layer == 0) {
            // X <- half(relu(acc + b2))
#pragma unroll
            for (int rt = 0; rt < 2; ++rt) {
                int r0 = rowbase + rt * 16 + g;
#pragma unroll
                for (int ct = 0; ct < 8; ++ct) {
                    int col = colbase + ct * 8 + t * 2;
                    float ba = bias[col], bb = bias[col + 1];
                    *(__half2*)(Xs + (size_t)r0 * LDXH + col) =
                        __floats2half2_rn(fmaxf(acc[rt][ct][0] + ba, 0.f),
                                          fmaxf(acc[rt][ct][1] + bb, 0.f));
                    *(__half2*)(Xs + (size_t)(r0 + 8) * LDXH + col) =
                        __floats2half2_rn(fmaxf(acc[rt][ct][2] + ba, 0.f),
                                          fmaxf(acc[rt][ct][3] + bb, 0.f));
                }
            }
            __syncthreads();
        } else {
            // gene-sum of relu(acc + b3) over valid rows -> pool[b]
            float* red = (float*)(smem + X_BYTES);  // slot 0 (drained)
            if (tid < 512) red[tid] = 0.f;
            __syncthreads();
#pragma unroll
            for (int ct = 0; ct < 8; ++ct) {
                int col = colbase + ct * 8 + t * 2;
#pragma unroll
                for (int j = 0; j < 2; ++j) {
                    float bv = bias[col + j];
                    float s = 0.f;
#pragma unroll
                    for (int rt = 0; rt < 2; ++rt) {
                        int r0 = rowbase + rt * 16 + g;
                        if (r0 < valid)     s += fmaxf(acc[rt][ct][j] + bv, 0.f);
                        if (r0 + 8 < valid) s += fmaxf(acc[rt][ct][2 + j] + bv, 0.f);
                    }
                    s += __shfl_xor_sync(0xFFFFFFFFu, s, 4);
                    s += __shfl_xor_sync(0xFFFFFFFFu, s, 8);
                    s += __shfl_xor_sync(0xFFFFFFFFu, s, 16);
                    if (g == 0) atomicAdd(&red[col + j], s);
                }
            }
            __syncthreads();
            if (tid < 512) atomicAdd(&pool[(size_t)b * H2 + tid], red[tid]);
        }
    }
}

// ---------------- launch ----------------
extern "C" void kernel_launch(void* const* d_in, const int* in_sizes, int n_in,
                              void* d_out, int out_size) {
    const float* mol  = (const float*)d_in[0];
    const float* gene = (const float*)d_in[1];
    const int*   ei   = (const int*)d_in[2];
    const float* g1w  = (const float*)d_in[3];
    const float* g1b  = (const float*)d_in[4];
    const float* g2w  = (const float*)d_in[5];
    const float* g2b  = (const float*)d_in[6];
    const float* f1w  = (const float*)d_in[7];
    const float* f1b  = (const float*)d_in[8];
    const float* f2w  = (const float*)d_in[9];
    const float* f2b  = (const float*)d_in[10];
    const float* f3w  = (const float*)d_in[11];
    const float* f3b  = (const float*)d_in[12];
    const float* f4w  = (const float*)d_in[13];
    const float* f4b  = (const float*)d_in[14];
    float* out = (float*)d_out;

    int E = in_sizes[2] / 2;
    const int* src = ei;
    const int* dst = ei + E;

    float *bufA, *bufB, *bufC, *hg, *hm, *pool, *f4p;
    __half *w2h, *w3h;
    cudaGetSymbolAddress((void**)&bufA, d_bufA);
    cudaGetSymbolAddress((void**)&bufB, d_bufB);
    cudaGetSymbolAddress((void**)&bufC, d_bufC);
    cudaGetSymbolAddress((void**)&hg, d_hg);
    cudaGetSymbolAddress((void**)&hm, d_hm);
    cudaGetSymbolAddress((void**)&pool, d_pool);
    cudaGetSymbolAddress((void**)&f4p, d_f4p);
    cudaGetSymbolAddress((void**)&w2h, d_w2h);
    cudaGetSymbolAddress((void**)&w3h, d_w3h);

    // prep (deg_init + fp16 weights + pool zero + padded f4w), then degree count
    k_prep<<<1024, 256>>>(f2w, f3w, f4w, w2h, w3h, pool);
    k_deg_count<<<(E + 255) / 256, 256>>>(dst, E);

    // GCN layer 1: bufA = gene@g1w (raw), bufB = g1b + bufA*dinv^2, then edges
    sgemm_c<<<dim3(10, 31), 256>>>(gene, HD, g1w, HD, bufA, HD, NG, HD, HD, g1b, 1.0f, bufB, HD);
    k_scatter_edges4<<<(E * 75 + 255) / 256, 256>>>(bufA, bufB, src, dst, E);

    // GCN layer 2: bufA = bufB@g2w (raw), bufC = g2b + bufA*dinv^2, then edges
    sgemm_c<<<dim3(10, 31), 256>>>(bufB, HD, g2w, HD, bufA, HD, NG, HD, HD, g2b, 1.0f, bufC, HD);
    k_scatter_edges4<<<(E * 75 + 255) / 256, 256>>>(bufA, bufC, src, dst, E);

    // ffn1 split: hg = g2 @ W1[:300], hm = mol @ W1[300:]
    sgemm_c<<<dim3(16, 31), 256>>>(bufC, HD, f1w, H2, hg, H2, NG, H2, HD, nullptr, 1.0f, nullptr, H2);
    sgemm_c<<<dim3(16, 4), 256>>>(mol, HD, f1w + HD * H2, H2, hm, H2, NB, H2, HD, nullptr, 1.0f, nullptr, H2);

    // fused ffn2+ffn3+mean-partial on fp16 tensor cores
    cudaFuncSetAttribute(k_ffn_tc, cudaFuncAttributeMaxDynamicSharedMemorySize, SMEM_FFN);
    k_ffn_tc<<<dim3(16, NB), 512, SMEM_FFN>>>(hg, hm, f1b, w2h, f2b, w3h, f3b, pool);

    // out = (pool/978) @ f4p (padded, aligned) + ffn4_b; write bound 978
    sgemm_c<<<dim3(31, 4), 256>>>(pool, H2, f4p, 980, out, NG, NB, 980, H2, f4b, 1.0f / 978.0f, nullptr, NG);
}